// round 15
// baseline (speedup 1.0000x reference)
#include <cuda_runtime.h>

// ---------------------------------------------------------------------------
// RelationOnSpatial, algebraically collapsed:
//   f = softmax(s_theta[:,None]+s_phi[None,:],axis=1) == softmax(s_phi)
//   (theta path dead, all output rows identical; constant bias cancels).
//   z[i,c] = gamma * ( g_w[c,:,:] . q / S + g_b[c] )
//   q[cy,ky,kx] = sum_{h,w} y[cy,h,w] * e[h+1-ky, w+1-kx],  e=exp(s_phi), S=sum e
// ---------------------------------------------------------------------------

#define CY   256
#define H    128
#define WW   128
#define HW   16384
#define KEL  2304            // CY*9

__device__ float d_phi_part[32 * KEL];                // kA partials (32 chunks)
__device__ __align__(16) float d_sphi_part[32 * HW];  // conv partials per chunk
__device__ __align__(16) float d_e[HW];
__device__ float d_Spart[64];
__device__ __align__(16) float d_qe_w[16 * KEL];      // per-strip q partials
__device__ __align__(16) float d_q[KEL];
__device__ __align__(16) float d_r[256];
__device__ unsigned int d_ctr = 0;                    // kD last-block counter

// ---------------------------------------------------------------------------
// A: phi_eff partials over 32 chunks of 8 summed channels.  grid (9,32) x 256.
// ---------------------------------------------------------------------------
__global__ void kA(const float* __restrict__ phi_w,
                   const float* __restrict__ concat_w) {
    const int t   = threadIdx.x;
    const int out = blockIdx.x * 256 + t;
    const int p   = blockIdx.y;
    const float* wp = concat_w + 256;
    float s = 0.f;
    #pragma unroll
    for (int c = p * 8; c < p * 8 + 8; ++c)
        s += wp[c] * phi_w[c * KEL + out];
    d_phi_part[p * KEL + out] = s;
}

// ---------------------------------------------------------------------------
// B: 256ch -> 1ch 3x3 conv partials. grid (16 strips, 32 chunks of 8ch) x 256.
// Warp w owns channel chunk*8+w, sliding down the 8-row strip. y rows loaded
// in two batches of 5 (MLP=5), then shuffles, then FMAs. Cross-channel sum
// staged via disjoint smem tiles (fixed order).
// ---------------------------------------------------------------------------
__global__ void __launch_bounds__(256, 3) kB(const float* __restrict__ y) {
    __shared__ float kk[72];
    __shared__ __align__(16) float acc_sm[8][8][128];   // [warp][row][col]
    const int t = threadIdx.x;
    const int strip = blockIdx.x, chunk = blockIdx.y;

    if (t < 72) {
        float s = 0.f;
        #pragma unroll
        for (int p = 0; p < 32; ++p) s += d_phi_part[p * KEL + chunk * 72 + t];
        kk[t] = s;
    }
    __syncthreads();

    const int w = t >> 5, g = t & 31;
    const int cy = chunk * 8 + w;
    const int r0 = strip * 8;

    float k9[9];
    #pragma unroll
    for (int k = 0; k < 9; ++k) k9[k] = kk[w * 9 + k];

    float4 acc[8];
    #pragma unroll
    for (int o = 0; o < 8; ++o) acc[o] = make_float4(0.f, 0.f, 0.f, 0.f);

    const float* yb = y + cy * HW + 4 * g;
    const float4 Z = make_float4(0.f, 0.f, 0.f, 0.f);

    #pragma unroll
    for (int jb = 0; jb < 2; ++jb) {
        float4 V[5]; float L[5], R[5];
        #pragma unroll
        for (int i = 0; i < 5; ++i) {
            const int lr = r0 - 1 + jb * 5 + i;
            V[i] = (lr >= 0 && lr < H) ? *(const float4*)(yb + lr * WW) : Z;
        }
        #pragma unroll
        for (int i = 0; i < 5; ++i) {
            L[i] = __shfl_up_sync(~0u, V[i].w, 1);   if (g == 0)  L[i] = 0.f;
            R[i] = __shfl_down_sync(~0u, V[i].x, 1); if (g == 31) R[i] = 0.f;
        }
        #pragma unroll
        for (int i = 0; i < 5; ++i) {
            const int j = jb * 5 + i;
            #pragma unroll
            for (int ky = 0; ky < 3; ++ky) {
                const int lo = j - ky;
                if (lo >= 0 && lo < 8) {
                    const float k0 = k9[ky * 3 + 0];
                    const float k1 = k9[ky * 3 + 1];
                    const float k2 = k9[ky * 3 + 2];
                    acc[lo].x += k0 * L[i]   + k1 * V[i].x + k2 * V[i].y;
                    acc[lo].y += k0 * V[i].x + k1 * V[i].y + k2 * V[i].z;
                    acc[lo].z += k0 * V[i].y + k1 * V[i].z + k2 * V[i].w;
                    acc[lo].w += k0 * V[i].z + k1 * V[i].w + k2 * R[i];
                }
            }
        }
    }

    #pragma unroll
    for (int o = 0; o < 8; ++o)
        *(float4*)&acc_sm[w][o][4 * g] = acc[o];
    __syncthreads();

    float4 s = make_float4(0.f, 0.f, 0.f, 0.f);
    #pragma unroll
    for (int b = 0; b < 8; ++b) {
        const float4 v = *(const float4*)&acc_sm[b][w][4 * g];
        s.x += v.x; s.y += v.y; s.z += v.z; s.w += v.w;
    }
    *(float4*)&d_sphi_part[chunk * HW + (r0 + w) * WW + 4 * g] = s;
}

// ---------------------------------------------------------------------------
// C: e = exp(sum of 32 chunk partials); S partials.  grid 64 x 256.
// 4 threads cooperate per float4-element (each sums 8 chunks, LDG.128).
// ---------------------------------------------------------------------------
__global__ void kC() {
    __shared__ __align__(16) float4 buf[4][64];
    __shared__ float red[2];
    const int t = threadIdx.x;
    const int lq  = t & 63;
    const int sub = t >> 6;
    const int q4  = blockIdx.x * 64 + lq;

    float4 s = make_float4(0.f, 0.f, 0.f, 0.f);
    #pragma unroll
    for (int p = sub * 8; p < sub * 8 + 8; ++p) {
        const float4 v = ((const float4*)(d_sphi_part + p * HW))[q4];
        s.x += v.x; s.y += v.y; s.z += v.z; s.w += v.w;
    }
    buf[sub][lq] = s;
    __syncthreads();

    float v = 0.f;
    if (t < 64) {
        const float4 a = buf[0][t], b = buf[1][t], c = buf[2][t], d = buf[3][t];
        float4 e;
        e.x = __expf(a.x + b.x + c.x + d.x);
        e.y = __expf(a.y + b.y + c.y + d.y);
        e.z = __expf(a.z + b.z + c.z + d.z);
        e.w = __expf(a.w + b.w + c.w + d.w);
        ((float4*)d_e)[blockIdx.x * 64 + t] = e;
        v = e.x + e.y + e.z + e.w;
        #pragma unroll
        for (int o = 16; o; o >>= 1) v += __shfl_xor_sync(~0u, v, o);
        if ((t & 31) == 0) red[t >> 5] = v;
    }
    __syncthreads();
    if (t == 0) d_Spart[blockIdx.x] = red[0] + red[1];
}

// ---------------------------------------------------------------------------
// D: q partials + folded strip-reduction (last block).
// grid (16 strips of 8 rows, 32 channel-octets) x 256.
// SMEM-free e path with a 4-slot register window: row j+3 is prefetched one
// full iteration before use and each slot's halo shuffles run one full
// iteration after its load, so the per-row critical path is pure FMA.
//   iter j: E[0]=row j-1, E[1]=row j, E[2]=row j+1 (h0-relative), E[3]=row j+2
//   a[3ky+kx]: e col = w+1-kx; slot ii = 2-ky.
// ---------------------------------------------------------------------------
__global__ void __launch_bounds__(256, 4) kD(const float* __restrict__ y) {
    __shared__ float redsm[72];
    __shared__ int isLast;
    const int t = threadIdx.x;
    const int strip = blockIdx.x;   // 0..15
    const int oct   = blockIdx.y;   // 0..31
    const int h0 = strip * 8;

    const int w = t >> 5, g = t & 31;
    const int cy = oct * 8 + w;
    const float* yb = y + cy * HW + h0 * WW + 4 * g;
    const float* eb = d_e + 4 * g;
    const float4 Z = make_float4(0.f, 0.f, 0.f, 0.f);

    float a[9];
    #pragma unroll
    for (int k = 0; k < 9; ++k) a[k] = 0.f;

    // init window: E[i] = e row h0-1+i, i=0..3 (4 independent loads)
    float4 E[4]; float L[3], R[3];
    #pragma unroll
    for (int i = 0; i < 4; ++i) {
        const int gr = h0 - 1 + i;
        E[i] = (gr >= 0 && gr < H) ? *(const float4*)(eb + gr * WW) : Z;
    }
    #pragma unroll
    for (int i = 0; i < 2; ++i) {
        L[i] = __shfl_up_sync(~0u, E[i].w, 1);   if (g == 0)  L[i] = 0.f;
        R[i] = __shfl_down_sync(~0u, E[i].x, 1); if (g == 31) R[i] = 0.f;
    }

    #pragma unroll
    for (int jb = 0; jb < 2; ++jb) {
        float4 yv[4];
        #pragma unroll
        for (int i = 0; i < 4; ++i)
            yv[i] = *(const float4*)(yb + (jb * 4 + i) * WW);

        #pragma unroll
        for (int i = 0; i < 4; ++i) {
            const int j = jb * 4 + i;
            // halo shuffles for slot 2 (row loaded one full iteration ago)
            L[2] = __shfl_up_sync(~0u, E[2].w, 1);   if (g == 0)  L[2] = 0.f;
            R[2] = __shfl_down_sync(~0u, E[2].x, 1); if (g == 31) R[2] = 0.f;

            #pragma unroll
            for (int ky = 0; ky < 3; ++ky) {
                const int ii = 2 - ky;
                a[3*ky+1] += yv[i].x*E[ii].x + yv[i].y*E[ii].y + yv[i].z*E[ii].z + yv[i].w*E[ii].w;
                a[3*ky+0] += yv[i].x*E[ii].y + yv[i].y*E[ii].z + yv[i].z*E[ii].w + yv[i].w*R[ii];
                a[3*ky+2] += yv[i].x*L[ii]   + yv[i].y*E[ii].x + yv[i].z*E[ii].y + yv[i].w*E[ii].z;
            }

            // shift window; prefetch row h0+j+3 (only needed through j=5)
            E[0] = E[1]; L[0] = L[1]; R[0] = R[1];
            E[1] = E[2]; L[1] = L[2]; R[1] = R[2];
            E[2] = E[3];
            if (j < 6) {
                const int gr = h0 + j + 3;
                E[3] = (gr < H) ? *(const float4*)(eb + gr * WW) : Z;
            }
        }
    }

    #pragma unroll
    for (int k = 0; k < 9; ++k)
        #pragma unroll
        for (int o = 16; o; o >>= 1)
            a[k] += __shfl_xor_sync(~0u, a[k], o);

    if (g == 0) {
        #pragma unroll
        for (int k = 0; k < 9; ++k) redsm[w * 9 + k] = a[k];
    }
    __syncthreads();
    if (t < 72) {
        const int ch = t / 9, k = t - ch * 9;
        d_qe_w[strip * KEL + (oct * 8 + ch) * 9 + k] = redsm[t];
    }

    // ---- folded kE0: last block reduces 16 strip-partials -> d_q ----
    __threadfence();
    __syncthreads();
    if (t == 0) isLast = (atomicAdd(&d_ctr, 1u) == 16u * 32u - 1u) ? 1 : 0;
    __syncthreads();
    if (isLast) {
        __threadfence();
        for (int j4 = t; j4 < 576; j4 += 256) {   // 576 float4 = 2304 floats
            float4 s = make_float4(0.f, 0.f, 0.f, 0.f);
            #pragma unroll
            for (int sb = 0; sb < 16; ++sb) {
                const float4 v = ((const float4*)(d_qe_w + sb * KEL))[j4];
                s.x += v.x; s.y += v.y; s.z += v.z; s.w += v.w;
            }
            ((float4*)d_q)[j4] = s;
        }
        if (t == 0) d_ctr = 0;   // reset for graph replay
    }
}

// ---------------------------------------------------------------------------
// E: r[c] = gamma*(g_w[c,:].q / S + g_b[c]).  256 blocks x 256.
// ---------------------------------------------------------------------------
__global__ void kE(const float* __restrict__ g_w,
                   const float* __restrict__ g_b,
                   const float* __restrict__ gamma) {
    __shared__ float red[256];
    const int c = blockIdx.x, t = threadIdx.x;
    const float4* gw4 = (const float4*)(g_w + c * KEL);
    const float4* q4  = (const float4*)d_q;
    float s = 0.f;
    for (int j = t; j < 576; j += 256) {
        const float4 gv = gw4[j];
        const float4 qv = q4[j];
        s += gv.x * qv.x + gv.y * qv.y + gv.z * qv.z + gv.w * qv.w;
    }
    red[t] = s;
    __syncthreads();
    for (int o = 128; o > 0; o >>= 1) {
        if (t < o) red[t] += red[t + o];
        __syncthreads();
    }
    if (t == 0) {
        float S = 0.f;
        #pragma unroll
        for (int i = 0; i < 64; ++i) S += d_Spart[i];
        d_r[c] = gamma[0] * (red[0] / S + g_b[c]);
    }
}

// ---------------------------------------------------------------------------
// F: broadcast r to 1024 rows, float4.  256 x 256.
// ---------------------------------------------------------------------------
__global__ void kF(float* __restrict__ out) {
    const int i = blockIdx.x * 256 + threadIdx.x;
    ((float4*)out)[i] = ((const float4*)d_r)[i & 63];
}

extern "C" void kernel_launch(void* const* d_in, const int* in_sizes, int n_in,
                              void* d_out, int out_size) {
    // order: x, y, g_w, g_b, phi_w, phi_b, theta_w, theta_b, concat_w, gamma
    const float* y        = (const float*)d_in[1];
    const float* g_w      = (const float*)d_in[2];
    const float* g_b      = (const float*)d_in[3];
    const float* phi_w    = (const float*)d_in[4];
    const float* concat_w = (const float*)d_in[8];
    const float* gamma    = (const float*)d_in[9];

    kA<<<dim3(9, 32), 256>>>(phi_w, concat_w);
    kB<<<dim3(16, 32), 256>>>(y);
    kC<<<64, 256>>>();
    kD<<<dim3(16, 32), 256>>>(y);
    kE<<<256, 256>>>(g_w, g_b, gamma);
    kF<<<256, 256>>>((float*)d_out);
}

// round 16
// speedup vs baseline: 1.2947x; 1.2947x over previous
#include <cuda_runtime.h>

// ---------------------------------------------------------------------------
// RelationOnSpatial, algebraically collapsed:
//   f = softmax(s_theta[:,None]+s_phi[None,:],axis=1) == softmax(s_phi)
//   (theta path dead, all output rows identical; constant bias cancels).
//   z[i,c] = gamma * ( g_w[c,:,:] . q / S + g_b[c] )
//   q[cy,ky,kx] = sum_{h,w} y[cy,h,w] * e[h+1-ky, w+1-kx],  e=exp(s_phi), S=sum e
// Kernels chained with PDL (programmatic dependent launch) to hide launch gaps.
// ---------------------------------------------------------------------------

#define CY   256
#define H    128
#define WW   128
#define HW   16384
#define KEL  2304            // CY*9

__device__ float d_phi_part[32 * KEL];                // kA partials (32 chunks)
__device__ __align__(16) float d_sphi_part[32 * HW];  // conv partials per chunk
__device__ __align__(16) float d_e[HW];
__device__ float d_Spart[64];
__device__ __align__(16) float d_qe_w[16 * KEL];      // per-strip q partials
__device__ __align__(16) float d_q[KEL];
__device__ __align__(16) float d_r[256];

// ---------------------------------------------------------------------------
// A: phi_eff partials over 32 chunks of 8 summed channels.  grid (9,32) x 256.
// ---------------------------------------------------------------------------
__global__ void kA(const float* __restrict__ phi_w,
                   const float* __restrict__ concat_w) {
    const int t   = threadIdx.x;
    const int out = blockIdx.x * 256 + t;
    const int p   = blockIdx.y;
    const float* wp = concat_w + 256;
    float s = 0.f;
    #pragma unroll
    for (int c = p * 8; c < p * 8 + 8; ++c)
        s += wp[c] * phi_w[c * KEL + out];
    d_phi_part[p * KEL + out] = s;
}

// ---------------------------------------------------------------------------
// B: 256ch -> 1ch 3x3 conv partials. grid (16 strips, 32 chunks of 8ch) x 256.
// Warp w owns channel chunk*8+w, sliding down the 8-row strip. y rows loaded
// in two batches of 5 (MLP=5), then shuffles, then FMAs. Cross-channel sum
// staged via disjoint smem tiles (fixed order).
// ---------------------------------------------------------------------------
__global__ void __launch_bounds__(256, 3) kB(const float* __restrict__ y) {
    __shared__ float kk[72];
    __shared__ __align__(16) float acc_sm[8][8][128];   // [warp][row][col]
    const int t = threadIdx.x;
    const int strip = blockIdx.x, chunk = blockIdx.y;

    cudaGridDependencySynchronize();   // wait for kA's d_phi_part

    if (t < 72) {
        float s = 0.f;
        #pragma unroll
        for (int p = 0; p < 32; ++p) s += d_phi_part[p * KEL + chunk * 72 + t];
        kk[t] = s;
    }
    __syncthreads();

    const int w = t >> 5, g = t & 31;
    const int cy = chunk * 8 + w;
    const int r0 = strip * 8;

    float k9[9];
    #pragma unroll
    for (int k = 0; k < 9; ++k) k9[k] = kk[w * 9 + k];

    float4 acc[8];
    #pragma unroll
    for (int o = 0; o < 8; ++o) acc[o] = make_float4(0.f, 0.f, 0.f, 0.f);

    const float* yb = y + cy * HW + 4 * g;
    const float4 Z = make_float4(0.f, 0.f, 0.f, 0.f);

    #pragma unroll
    for (int jb = 0; jb < 2; ++jb) {
        float4 V[5]; float L[5], R[5];
        #pragma unroll
        for (int i = 0; i < 5; ++i) {
            const int lr = r0 - 1 + jb * 5 + i;
            V[i] = (lr >= 0 && lr < H) ? *(const float4*)(yb + lr * WW) : Z;
        }
        #pragma unroll
        for (int i = 0; i < 5; ++i) {
            L[i] = __shfl_up_sync(~0u, V[i].w, 1);   if (g == 0)  L[i] = 0.f;
            R[i] = __shfl_down_sync(~0u, V[i].x, 1); if (g == 31) R[i] = 0.f;
        }
        #pragma unroll
        for (int i = 0; i < 5; ++i) {
            const int j = jb * 5 + i;
            #pragma unroll
            for (int ky = 0; ky < 3; ++ky) {
                const int lo = j - ky;
                if (lo >= 0 && lo < 8) {
                    const float k0 = k9[ky * 3 + 0];
                    const float k1 = k9[ky * 3 + 1];
                    const float k2 = k9[ky * 3 + 2];
                    acc[lo].x += k0 * L[i]   + k1 * V[i].x + k2 * V[i].y;
                    acc[lo].y += k0 * V[i].x + k1 * V[i].y + k2 * V[i].z;
                    acc[lo].z += k0 * V[i].y + k1 * V[i].z + k2 * V[i].w;
                    acc[lo].w += k0 * V[i].z + k1 * V[i].w + k2 * R[i];
                }
            }
        }
    }

    #pragma unroll
    for (int o = 0; o < 8; ++o)
        *(float4*)&acc_sm[w][o][4 * g] = acc[o];
    __syncthreads();

    float4 s = make_float4(0.f, 0.f, 0.f, 0.f);
    #pragma unroll
    for (int b = 0; b < 8; ++b) {
        const float4 v = *(const float4*)&acc_sm[b][w][4 * g];
        s.x += v.x; s.y += v.y; s.z += v.z; s.w += v.w;
    }
    *(float4*)&d_sphi_part[chunk * HW + (r0 + w) * WW + 4 * g] = s;
}

// ---------------------------------------------------------------------------
// C: e = exp(sum of 32 chunk partials); S partials.  grid 64 x 256.
// 4 threads cooperate per float4-element (each sums 8 chunks, LDG.128).
// ---------------------------------------------------------------------------
__global__ void kC() {
    __shared__ __align__(16) float4 buf[4][64];
    __shared__ float red[2];
    const int t = threadIdx.x;
    const int lq  = t & 63;
    const int sub = t >> 6;
    const int q4  = blockIdx.x * 64 + lq;

    cudaGridDependencySynchronize();   // wait for kB's d_sphi_part

    float4 s = make_float4(0.f, 0.f, 0.f, 0.f);
    #pragma unroll
    for (int p = sub * 8; p < sub * 8 + 8; ++p) {
        const float4 v = ((const float4*)(d_sphi_part + p * HW))[q4];
        s.x += v.x; s.y += v.y; s.z += v.z; s.w += v.w;
    }
    buf[sub][lq] = s;
    __syncthreads();

    float v = 0.f;
    if (t < 64) {
        const float4 a = buf[0][t], b = buf[1][t], c = buf[2][t], d = buf[3][t];
        float4 e;
        e.x = __expf(a.x + b.x + c.x + d.x);
        e.y = __expf(a.y + b.y + c.y + d.y);
        e.z = __expf(a.z + b.z + c.z + d.z);
        e.w = __expf(a.w + b.w + c.w + d.w);
        ((float4*)d_e)[blockIdx.x * 64 + t] = e;
        v = e.x + e.y + e.z + e.w;
        #pragma unroll
        for (int o = 16; o; o >>= 1) v += __shfl_xor_sync(~0u, v, o);
        if ((t & 31) == 0) red[t >> 5] = v;
    }
    __syncthreads();
    if (t == 0) d_Spart[blockIdx.x] = red[0] + red[1];
}

// ---------------------------------------------------------------------------
// D: q partials. grid (16 strips of 8 rows, 32 channel-octets) x 256.
// SMEM-free e path: e rows loaded directly (L1/L2-hot), col halo via 2
// shuffles per row, 3-row register window. One 9-value butterfly per warp.
//   a[3ky+kx]: e col = w+1-kx ->
//     kx=0: (E.y,E.z,E.w,R) ; kx=1: E ; kx=2: (L,E.x,E.y,E.z)
// ---------------------------------------------------------------------------
__global__ void __launch_bounds__(256, 4) kD(const float* __restrict__ y) {
    __shared__ float redsm[72];
    const int t = threadIdx.x;
    const int strip = blockIdx.x;   // 0..15
    const int oct   = blockIdx.y;   // 0..31
    const int h0 = strip * 8;

    const int w = t >> 5, g = t & 31;
    const int cy = oct * 8 + w;
    const float* yb = y + cy * HW + h0 * WW + 4 * g;
    const float* eb = d_e + 4 * g;
    const float4 Z = make_float4(0.f, 0.f, 0.f, 0.f);

    cudaGridDependencySynchronize();   // wait for kC's d_e

    float a[9];
    #pragma unroll
    for (int k = 0; k < 9; ++k) a[k] = 0.f;

    // e window W[i] = e row (h0 + j - 1 + i) at iteration j; init for j=0.
    float4 E[3]; float L[3], R[3];
    #pragma unroll
    for (int i = 0; i < 3; ++i) {
        const int gr = h0 - 1 + i;
        E[i] = (gr >= 0 && gr < H) ? *(const float4*)(eb + gr * WW) : Z;
        L[i] = __shfl_up_sync(~0u, E[i].w, 1);   if (g == 0)  L[i] = 0.f;
        R[i] = __shfl_down_sync(~0u, E[i].x, 1); if (g == 31) R[i] = 0.f;
    }

    #pragma unroll
    for (int jb = 0; jb < 2; ++jb) {
        float4 yv[4];
        #pragma unroll
        for (int i = 0; i < 4; ++i)
            yv[i] = *(const float4*)(yb + (jb * 4 + i) * WW);

        #pragma unroll
        for (int i = 0; i < 4; ++i) {
            const int j = jb * 4 + i;
            #pragma unroll
            for (int ky = 0; ky < 3; ++ky) {
                const int ii = 2 - ky;      // window slot for this ky
                a[3*ky+1] += yv[i].x*E[ii].x + yv[i].y*E[ii].y + yv[i].z*E[ii].z + yv[i].w*E[ii].w;
                a[3*ky+0] += yv[i].x*E[ii].y + yv[i].y*E[ii].z + yv[i].z*E[ii].w + yv[i].w*R[ii];
                a[3*ky+2] += yv[i].x*L[ii]   + yv[i].y*E[ii].x + yv[i].z*E[ii].y + yv[i].w*E[ii].z;
            }
            if (j < 7) {
                E[0] = E[1]; L[0] = L[1]; R[0] = R[1];
                E[1] = E[2]; L[1] = L[2]; R[1] = R[2];
                const int gr = h0 + j + 2;
                E[2] = (gr < H) ? *(const float4*)(eb + gr * WW) : Z;
                L[2] = __shfl_up_sync(~0u, E[2].w, 1);   if (g == 0)  L[2] = 0.f;
                R[2] = __shfl_down_sync(~0u, E[2].x, 1); if (g == 31) R[2] = 0.f;
            }
        }
    }

    #pragma unroll
    for (int k = 0; k < 9; ++k)
        #pragma unroll
        for (int o = 16; o; o >>= 1)
            a[k] += __shfl_xor_sync(~0u, a[k], o);

    if (g == 0) {
        #pragma unroll
        for (int k = 0; k < 9; ++k) redsm[w * 9 + k] = a[k];
    }
    __syncthreads();
    if (t < 72) {
        const int ch = t / 9, k = t - ch * 9;
        d_qe_w[strip * KEL + (oct * 8 + ch) * 9 + k] = redsm[t];
    }
}

// ---------------------------------------------------------------------------
// E0: q[j] = sum over 16 strips.  grid 9 x 256.
// ---------------------------------------------------------------------------
__global__ void kE0() {
    const int j = blockIdx.x * 256 + threadIdx.x;
    cudaGridDependencySynchronize();   // wait for kD's d_qe_w
    float s = 0.f;
    #pragma unroll
    for (int sb = 0; sb < 16; ++sb) s += d_qe_w[sb * KEL + j];
    d_q[j] = s;
}

// ---------------------------------------------------------------------------
// E: r[c] = gamma*(g_w[c,:].q / S + g_b[c]).  256 blocks x 256.
// ---------------------------------------------------------------------------
__global__ void kE(const float* __restrict__ g_w,
                   const float* __restrict__ g_b,
                   const float* __restrict__ gamma) {
    __shared__ float red[256];
    const int c = blockIdx.x, t = threadIdx.x;
    const float4* gw4 = (const float4*)(g_w + c * KEL);
    const float4* q4  = (const float4*)d_q;

    cudaGridDependencySynchronize();   // wait for kE0's d_q

    float s = 0.f;
    for (int j = t; j < 576; j += 256) {
        const float4 gv = gw4[j];
        const float4 qv = q4[j];
        s += gv.x * qv.x + gv.y * qv.y + gv.z * qv.z + gv.w * qv.w;
    }
    red[t] = s;
    __syncthreads();
    for (int o = 128; o > 0; o >>= 1) {
        if (t < o) red[t] += red[t + o];
        __syncthreads();
    }
    if (t == 0) {
        float S = 0.f;
        #pragma unroll
        for (int i = 0; i < 64; ++i) S += d_Spart[i];
        d_r[c] = gamma[0] * (red[0] / S + g_b[c]);
    }
}

// ---------------------------------------------------------------------------
// F: broadcast r to 1024 rows, float4.  256 x 256.
// ---------------------------------------------------------------------------
__global__ void kF(float* __restrict__ out) {
    const int i = blockIdx.x * 256 + threadIdx.x;
    cudaGridDependencySynchronize();   // wait for kE's d_r
    ((float4*)out)[i] = ((const float4*)d_r)[i & 63];
}

// ---------------------------------------------------------------------------
// Host: PDL-chained launches (launch overhead overlaps predecessor tail).
// ---------------------------------------------------------------------------
template <typename F, typename... Args>
static inline void launch_pdl(F func, dim3 grid, dim3 block, Args... args) {
    cudaLaunchConfig_t cfg = {};
    cfg.gridDim = grid;
    cfg.blockDim = block;
    cfg.dynamicSmemBytes = 0;
    cfg.stream = 0;
    cudaLaunchAttribute at[1];
    at[0].id = cudaLaunchAttributeProgrammaticStreamSerialization;
    at[0].val.programmaticStreamSerializationAllowed = 1;
    cfg.attrs = at;
    cfg.numAttrs = 1;
    cudaLaunchKernelEx(&cfg, func, args...);
}

extern "C" void kernel_launch(void* const* d_in, const int* in_sizes, int n_in,
                              void* d_out, int out_size) {
    // order: x, y, g_w, g_b, phi_w, phi_b, theta_w, theta_b, concat_w, gamma
    const float* y        = (const float*)d_in[1];
    const float* g_w      = (const float*)d_in[2];
    const float* g_b      = (const float*)d_in[3];
    const float* phi_w    = (const float*)d_in[4];
    const float* concat_w = (const float*)d_in[8];
    const float* gamma    = (const float*)d_in[9];

    kA<<<dim3(9, 32), 256>>>(phi_w, concat_w);
    launch_pdl(kB,  dim3(16, 32), dim3(256), y);
    launch_pdl(kC,  dim3(64),     dim3(256));
    launch_pdl(kD,  dim3(16, 32), dim3(256), y);
    launch_pdl(kE0, dim3(9),      dim3(256));
    launch_pdl(kE,  dim3(256),    dim3(256), g_w, g_b, gamma);
    launch_pdl(kF,  dim3(256),    dim3(256), (float*)d_out);
}